// round 6
// baseline (speedup 1.0000x reference)
#include <cuda_runtime.h>
#include <math.h>

#define BATCH   32
#define NTOK    197
#define DIM     768
#define HEADS   12
#define HD      64
#define MLPD    3072
#define DEPTH   12
#define ROWS    (BATCH*NTOK)     // 6304
#define NPATCH  196
#define PROWS   (BATCH*NPATCH)   // 6272
#define ATTN_SCALE 0.125f

// ---------------- scratch (no cudaMalloc allowed) ----------------
__device__ float g_patches[PROWS*DIM];
__device__ float g_h     [ROWS*DIM];
__device__ float g_ln    [ROWS*DIM];
__device__ float g_qkv   [ROWS*3*DIM];
__device__ float g_attno [ROWS*DIM];
__device__ float g_mlp   [ROWS*MLPD];
__device__ float g_cls   [BATCH*DIM];

// ---------------- helpers ----------------
__device__ __forceinline__ float gelu_exact(float x) {
    return 0.5f * x * (1.0f + erff(x * 0.70710678118654752f));
}

// block reduce over 256 threads. do_max=true -> max else sum.
__device__ __forceinline__ float blk_reduce256(float v, bool do_max, float* red) {
    #pragma unroll
    for (int off = 16; off; off >>= 1) {
        float o = __shfl_xor_sync(0xffffffffu, v, off);
        v = do_max ? fmaxf(v, o) : (v + o);
    }
    int w = threadIdx.x >> 5;
    if ((threadIdx.x & 31) == 0) red[w] = v;
    __syncthreads();
    if (threadIdx.x < 32) {
        v = red[threadIdx.x & 7];
        #pragma unroll
        for (int off = 4; off; off >>= 1) {
            float o = __shfl_xor_sync(0xffffffffu, v, off);
            v = do_max ? fmaxf(v, o) : (v + o);
        }
        if (threadIdx.x == 0) red[0] = v;
    }
    __syncthreads();
    float r = red[0];
    __syncthreads();   // protect red[] reuse by a following reduce
    return r;
}

// ---------------- patch gather ----------------
// P[m][k], m=b*196+t (t=ph*14+pw), k=c*256+py*16+px
__global__ void gather_patches_kernel(const float* __restrict__ x, float* __restrict__ P) {
    int idx = blockIdx.x * blockDim.x + threadIdx.x;
    int total = PROWS * DIM;
    if (idx >= total) return;
    int m = idx / DIM, k = idx - m * DIM;
    int b = m / NPATCH, t = m - b * NPATCH;
    int ph = t / 14, pw = t - ph * 14;
    int c = k >> 8, r = k & 255;
    int py = r >> 4, px = r & 15;
    int h = ph * 16 + py, w = pw * 16 + px;
    P[idx] = x[(((long)b * 3 + c) * 224 + h) * 224 + w];
}

// ---------------- assemble h = [cls ; tok] + pos ----------------
__global__ void embed_kernel(const float* __restrict__ tok, const float* __restrict__ cls,
                             const float* __restrict__ pos, float* __restrict__ h) {
    int idx = blockIdx.x * blockDim.x + threadIdx.x;
    int total = ROWS * DIM;
    if (idx >= total) return;
    int rd = idx % (NTOK * DIM);
    int b  = idx / (NTOK * DIM);
    int n  = rd / DIM, d = rd - n * DIM;
    float base = (n == 0) ? cls[d] : tok[((long)b * NPATCH + (n - 1)) * DIM + d];
    h[idx] = base + pos[n * DIM + d];
}

// ---------------- layernorm (768-wide rows, 256 threads/row) ----------------
__global__ void ln_kernel(const float* __restrict__ x, long row_stride,
                          const float* __restrict__ w, const float* __restrict__ b,
                          float* __restrict__ y) {
    __shared__ float red[8];
    long row = blockIdx.x;
    const float* xr = x + row * row_stride;
    int tid = threadIdx.x;
    float v[3], s = 0.f, ss = 0.f;
    #pragma unroll
    for (int i = 0; i < 3; i++) {
        float t = xr[tid + i * 256];
        v[i] = t; s += t; ss += t * t;
    }
    s  = blk_reduce256(s,  false, red);
    ss = blk_reduce256(ss, false, red);
    float mu  = s * (1.0f / 768.0f);
    float var = ss * (1.0f / 768.0f) - mu * mu;
    float inv = rsqrtf(var + 1e-5f);
    #pragma unroll
    for (int i = 0; i < 3; i++) {
        int d = tid + i * 256;
        y[row * DIM + d] = (v[i] - mu) * inv * w[d] + b[d];
    }
}

// ---------------- GEMM: C[M,N] = A[M,K] @ W[N,K]^T (+bias)(+resid)(gelu) ----------------
#define BM 64
#define BN 64
#define BK 16
__global__ __launch_bounds__(256) void gemm_nt_kernel(
        const float* __restrict__ A, const float* __restrict__ W,
        const float* __restrict__ bias, const float* __restrict__ resid,
        float* __restrict__ C, int M, int N, int K, int act /*1=gelu*/) {
    __shared__ float As[BK][BM];
    __shared__ float Ws[BK][BN];
    int bm = blockIdx.y * BM;
    int bn = blockIdx.x * BN;
    int tid = threadIdx.x;
    int lr = tid >> 2;            // 0..63
    int lc = (tid & 3) << 2;      // 0,4,8,12
    int tm = (tid >> 4) << 2;     // 0..60
    int tn = (tid & 15) << 2;     // 0..60
    float acc[4][4];
    #pragma unroll
    for (int i = 0; i < 4; i++)
        #pragma unroll
        for (int j = 0; j < 4; j++) acc[i][j] = 0.f;

    for (int kt = 0; kt < K; kt += BK) {
        // load A tile
        {
            int gr = bm + lr;
            float4 a4 = make_float4(0.f, 0.f, 0.f, 0.f);
            if (gr < M) a4 = *(const float4*)(A + (long)gr * K + kt + lc);
            As[lc + 0][lr] = a4.x; As[lc + 1][lr] = a4.y;
            As[lc + 2][lr] = a4.z; As[lc + 3][lr] = a4.w;
        }
        // load W tile
        {
            int gr = bn + lr;
            float4 w4 = make_float4(0.f, 0.f, 0.f, 0.f);
            if (gr < N) w4 = *(const float4*)(W + (long)gr * K + kt + lc);
            Ws[lc + 0][lr] = w4.x; Ws[lc + 1][lr] = w4.y;
            Ws[lc + 2][lr] = w4.z; Ws[lc + 3][lr] = w4.w;
        }
        __syncthreads();
        #pragma unroll
        for (int k = 0; k < BK; k++) {
            float4 av = *(const float4*)&As[k][tm];
            float4 wv = *(const float4*)&Ws[k][tn];
            float ar[4] = {av.x, av.y, av.z, av.w};
            float wr[4] = {wv.x, wv.y, wv.z, wv.w};
            #pragma unroll
            for (int i = 0; i < 4; i++)
                #pragma unroll
                for (int j = 0; j < 4; j++)
                    acc[i][j] = fmaf(ar[i], wr[j], acc[i][j]);
        }
        __syncthreads();
    }
    #pragma unroll
    for (int i = 0; i < 4; i++) {
        int row = bm + tm + i;
        if (row >= M) continue;
        #pragma unroll
        for (int j = 0; j < 4; j++) {
            int col = bn + tn + j;
            if (col >= N) continue;
            float v = acc[i][j];
            if (bias)  v += bias[col];
            if (resid) v += resid[(long)row * N + col];
            if (act == 1) v = gelu_exact(v);
            C[(long)row * N + col] = v;
        }
    }
}

// ---------------- attention: one block per (b,h) ----------------
// smem: Ks[197*64] Vs[197*64] qs[64] scores[208] part[256] red[8]
#define ATTN_SMEM_FLOATS (NTOK*HD*2 + 64 + 208 + 256 + 8)
__global__ __launch_bounds__(256) void attn_kernel(
        const float* __restrict__ qkv, float* __restrict__ o,
        const float* __restrict__ alpha, const float* __restrict__ beta,
        const float* __restrict__ gamma, int poly) {
    extern __shared__ float sh[];
    float* Ks     = sh;
    float* Vs     = Ks + NTOK * HD;
    float* qs     = Vs + NTOK * HD;
    float* scores = qs + 64;
    float* part   = scores + 208;
    float* red    = part + 256;

    int b = blockIdx.x / HEADS;
    int hh = blockIdx.x - b * HEADS;
    int tid = threadIdx.x;

    const float* kbase = qkv + (long)(b * NTOK) * (3 * DIM) + DIM + hh * HD;
    const float* vbase = kbase + DIM;
    // stage K, V (float4)
    for (int i = tid; i < NTOK * (HD / 4); i += 256) {
        int n = i >> 4, d4 = (i & 15) << 2;
        ((float4*)Ks)[i] = *(const float4*)(kbase + (long)n * (3 * DIM) + d4);
        ((float4*)Vs)[i] = *(const float4*)(vbase + (long)n * (3 * DIM) + d4);
    }
    float ah = alpha[hh], bh = beta[hh], gh = gamma[hh];
    __syncthreads();

    for (int n = 0; n < NTOK; n++) {
        const float* qrow = qkv + (long)(b * NTOK + n) * (3 * DIM) + hh * HD;
        if (tid < HD) qs[tid] = qrow[tid];
        __syncthreads();

        float sraw = 0.f;
        if (tid < NTOK) {
            const float* kr = Ks + tid * HD;
            float d0 = 0.f;
            #pragma unroll 16
            for (int d = 0; d < HD; d++) d0 = fmaf(qs[d], kr[d], d0);
            sraw = d0 * ATTN_SCALE;
        }

        float denom;
        if (poly) {
            float val = 0.f;
            if (tid < NTOK) {
                val = fmaxf(fmaf(ah * sraw, sraw, fmaf(bh, sraw, gh)), 0.f);
                scores[tid] = val;
            }
            denom = blk_reduce256(tid < NTOK ? val : 0.f, false, red) + 1e-6f;
        } else {
            float mx = blk_reduce256(tid < NTOK ? sraw : -1e30f, true, red);
            float p = 0.f;
            if (tid < NTOK) { p = __expf(sraw - mx); scores[tid] = p; }
            denom = blk_reduce256(p, false, red);
        }
        float inv = 1.0f / denom;

        // A @ V : 4 chunks x 64 dims
        int ch = tid >> 6, d = tid & 63;
        float a0 = 0.f;
        int m0 = ch * 50, m1 = m0 + 50; if (m1 > NTOK) m1 = NTOK;
        #pragma unroll 4
        for (int m = m0; m < m1; m++) a0 = fmaf(scores[m], Vs[m * HD + d], a0);
        part[ch * 64 + d] = a0;
        __syncthreads();
        if (tid < 64) {
            float t = part[tid] + part[64 + tid] + part[128 + tid] + part[192 + tid];
            o[(long)(b * NTOK + n) * DIM + hh * HD + tid] = t * inv;
        }
        __syncthreads();
    }
}

// ---------------- host ----------------
static inline dim3 gemm_grid(int M, int N) {
    return dim3((N + BN - 1) / BN, (M + BM - 1) / BM);
}

extern "C" void kernel_launch(void* const* d_in, const int* in_sizes, int n_in,
                              void* d_out, int out_size) {
    const float* x        = (const float*)d_in[0];
    const float* patch_w  = (const float*)d_in[1];
    const float* patch_b  = (const float*)d_in[2];
    const float* cls_tok  = (const float*)d_in[3];
    const float* pos_emb  = (const float*)d_in[4];
    const float* ln1_w    = (const float*)d_in[5];
    const float* ln1_b    = (const float*)d_in[6];
    const float* qkv_w    = (const float*)d_in[7];
    const float* proj_w   = (const float*)d_in[8];
    const float* proj_b   = (const float*)d_in[9];
    const float* ln2_w    = (const float*)d_in[10];
    const float* ln2_b    = (const float*)d_in[11];
    const float* mlp_w1   = (const float*)d_in[12];
    const float* mlp_b1   = (const float*)d_in[13];
    const float* mlp_w2   = (const float*)d_in[14];
    const float* mlp_b2   = (const float*)d_in[15];
    const float* alpha    = (const float*)d_in[16];
    const float* beta     = (const float*)d_in[17];
    const float* gamma    = (const float*)d_in[18];
    const float* norm_w   = (const float*)d_in[19];
    const float* norm_b   = (const float*)d_in[20];
    const float* head_w   = (const float*)d_in[21];
    const float* head_b   = (const float*)d_in[22];
    float* out = (float*)d_out;

    float *ph, *hh, *lnb, *qkvb, *ob, *mb, *clsb;
    cudaGetSymbolAddress((void**)&ph,   g_patches);
    cudaGetSymbolAddress((void**)&hh,   g_h);
    cudaGetSymbolAddress((void**)&lnb,  g_ln);
    cudaGetSymbolAddress((void**)&qkvb, g_qkv);
    cudaGetSymbolAddress((void**)&ob,   g_attno);
    cudaGetSymbolAddress((void**)&mb,   g_mlp);
    cudaGetSymbolAddress((void**)&clsb, g_cls);

    const int attn_smem = ATTN_SMEM_FLOATS * sizeof(float);
    cudaFuncSetAttribute(attn_kernel, cudaFuncAttributeMaxDynamicSharedMemorySize, attn_smem);

    // 1) patchify + embed
    {
        int total = PROWS * DIM;
        gather_patches_kernel<<<(total + 255) / 256, 256>>>(x, ph);
        gemm_nt_kernel<<<gemm_grid(PROWS, DIM), 256>>>(ph, patch_w, patch_b, nullptr,
                                                       ob /*tok scratch*/, PROWS, DIM, DIM, 0);
        int tot2 = ROWS * DIM;
        embed_kernel<<<(tot2 + 255) / 256, 256>>>(ob, cls_tok, pos_emb, hh);
    }

    // 2) transformer layers
    for (int i = 0; i < DEPTH; i++) {
        int poly = (i % 2 == 0) ? 1 : 0;   // MASK = (T,F,T,F,...)
        // attn block
        ln_kernel<<<ROWS, 256>>>(hh, DIM, ln1_w + (long)i * DIM, ln1_b + (long)i * DIM, lnb);
        gemm_nt_kernel<<<gemm_grid(ROWS, 3 * DIM), 256>>>(lnb, qkv_w + (long)i * 3 * DIM * DIM,
                                                          nullptr, nullptr, qkvb,
                                                          ROWS, 3 * DIM, DIM, 0);
        attn_kernel<<<BATCH * HEADS, 256, attn_smem>>>(qkvb, ob,
                                                       alpha + (long)i * HEADS,
                                                       beta  + (long)i * HEADS,
                                                       gamma + (long)i * HEADS, poly);
        gemm_nt_kernel<<<gemm_grid(ROWS, DIM), 256>>>(ob, proj_w + (long)i * DIM * DIM,
                                                      proj_b + (long)i * DIM, hh, hh,
                                                      ROWS, DIM, DIM, 0);
        // mlp block
        ln_kernel<<<ROWS, 256>>>(hh, DIM, ln2_w + (long)i * DIM, ln2_b + (long)i * DIM, lnb);
        gemm_nt_kernel<<<gemm_grid(ROWS, MLPD), 256>>>(lnb, mlp_w1 + (long)i * MLPD * DIM,
                                                       mlp_b1 + (long)i * MLPD, nullptr, mb,
                                                       ROWS, MLPD, DIM, 1 /*gelu*/);
        gemm_nt_kernel<<<gemm_grid(ROWS, DIM), 256>>>(mb, mlp_w2 + (long)i * DIM * MLPD,
                                                      mlp_b2 + (long)i * DIM, hh, hh,
                                                      ROWS, DIM, MLPD, 0);
    }

    // 3) final LN on cls rows + head
    ln_kernel<<<BATCH, 256>>>(hh, (long)NTOK * DIM, norm_w, norm_b, clsb);
    gemm_nt_kernel<<<gemm_grid(BATCH, 1000), 256>>>(clsb, head_w, head_b, nullptr, out,
                                                    BATCH, 1000, DIM, 0);
}

// round 9
// speedup vs baseline: 1.1639x; 1.1639x over previous
#include <cuda_runtime.h>
#include <math.h>

#define BATCH   32
#define NTOK    197
#define DIM     768
#define HEADS   12
#define HD      64
#define MLPD    3072
#define DEPTH   12
#define ROWS    (BATCH*NTOK)     // 6304
#define NPATCH  196
#define PROWS   (BATCH*NPATCH)   // 6272
#define ATTN_SCALE 0.125f

// ---------------- scratch (no cudaMalloc allowed) ----------------
__device__ float g_patches[PROWS*DIM];
__device__ float g_h     [ROWS*DIM];
__device__ float g_ln    [ROWS*DIM];
__device__ float g_qkv   [ROWS*3*DIM];
__device__ float g_attno [ROWS*DIM];
__device__ float g_mlp   [ROWS*MLPD];
__device__ float g_cls   [BATCH*DIM];

// ---------------- helpers ----------------
__device__ __forceinline__ float gelu_exact(float x) {
    return 0.5f * x * (1.0f + erff(x * 0.70710678118654752f));
}

__device__ __forceinline__ unsigned f2tf32(float x) {
    unsigned r;
    asm("cvt.rna.tf32.f32 %0, %1;" : "=r"(r) : "f"(x));
    return r;
}

// block reduce over 256 threads. do_max=true -> max else sum.
__device__ __forceinline__ float blk_reduce256(float v, bool do_max, float* red) {
    #pragma unroll
    for (int off = 16; off; off >>= 1) {
        float o = __shfl_xor_sync(0xffffffffu, v, off);
        v = do_max ? fmaxf(v, o) : (v + o);
    }
    int w = threadIdx.x >> 5;
    if ((threadIdx.x & 31) == 0) red[w] = v;
    __syncthreads();
    if (threadIdx.x < 32) {
        v = red[threadIdx.x & 7];
        #pragma unroll
        for (int off = 4; off; off >>= 1) {
            float o = __shfl_xor_sync(0xffffffffu, v, off);
            v = do_max ? fmaxf(v, o) : (v + o);
        }
        if (threadIdx.x == 0) red[0] = v;
    }
    __syncthreads();
    float r = red[0];
    __syncthreads();
    return r;
}

// ---------------- patch gather ----------------
__global__ void gather_patches_kernel(const float* __restrict__ x, float* __restrict__ P) {
    int idx = blockIdx.x * blockDim.x + threadIdx.x;
    int total = PROWS * DIM;
    if (idx >= total) return;
    int m = idx / DIM, k = idx - m * DIM;
    int b = m / NPATCH, t = m - b * NPATCH;
    int ph = t / 14, pw = t - ph * 14;
    int c = k >> 8, r = k & 255;
    int py = r >> 4, px = r & 15;
    int h = ph * 16 + py, w = pw * 16 + px;
    P[idx] = x[(((long)b * 3 + c) * 224 + h) * 224 + w];
}

// ---------------- assemble h = [cls ; tok] + pos ----------------
__global__ void embed_kernel(const float* __restrict__ tok, const float* __restrict__ cls,
                             const float* __restrict__ pos, float* __restrict__ h) {
    int idx = blockIdx.x * blockDim.x + threadIdx.x;
    int total = ROWS * DIM;
    if (idx >= total) return;
    int rd = idx % (NTOK * DIM);
    int b  = idx / (NTOK * DIM);
    int n  = rd / DIM, d = rd - n * DIM;
    float base = (n == 0) ? cls[d] : tok[((long)b * NPATCH + (n - 1)) * DIM + d];
    h[idx] = base + pos[n * DIM + d];
}

// ---------------- layernorm ----------------
__global__ void ln_kernel(const float* __restrict__ x, long row_stride,
                          const float* __restrict__ w, const float* __restrict__ b,
                          float* __restrict__ y) {
    __shared__ float red[8];
    long row = blockIdx.x;
    const float* xr = x + row * row_stride;
    int tid = threadIdx.x;
    float v[3], s = 0.f, ss = 0.f;
    #pragma unroll
    for (int i = 0; i < 3; i++) {
        float t = xr[tid + i * 256];
        v[i] = t; s += t; ss += t * t;
    }
    s  = blk_reduce256(s,  false, red);
    ss = blk_reduce256(ss, false, red);
    float mu  = s * (1.0f / 768.0f);
    float var = ss * (1.0f / 768.0f) - mu * mu;
    float inv = rsqrtf(var + 1e-5f);
    #pragma unroll
    for (int i = 0; i < 3; i++) {
        int d = tid + i * 256;
        y[row * DIM + d] = (v[i] - mu) * inv * w[d] + b[d];
    }
}

// ---------------- 3xTF32 tensor-core GEMM ----------------
// C[M,N] = A[M,K] @ W[N,K]^T (+bias)(+resid)(gelu)
// block tile 128x128x16, 8 warps, each warp 64x32 via m16n8k8 tf32 mma.
// 3xTF32: a = a_hi + a_lo, product = a_hi*b_hi + a_hi*b_lo + a_lo*b_hi.
#define BM 128
#define BN 128
#define BK 16
#define SPITCH (BM + 4)   // padded smem row pitch

__global__ __launch_bounds__(256) void gemm_tc_kernel(
        const float* __restrict__ A, const float* __restrict__ W,
        const float* __restrict__ bias, const float* __restrict__ resid,
        float* __restrict__ C, int M, int N, int K, int act /*1=gelu*/) {
    __shared__ unsigned AsH[BK][SPITCH];
    __shared__ unsigned AsL[BK][SPITCH];
    __shared__ unsigned WsH[BK][SPITCH];
    __shared__ unsigned WsL[BK][SPITCH];

    int bm = blockIdx.y * BM;
    int bn = blockIdx.x * BN;
    int tid  = threadIdx.x;
    int warp = tid >> 5;
    int lane = tid & 31;
    int g    = lane >> 2;    // 0..7
    int t4   = lane & 3;     // 0..3

    int wm = (warp & 1) * 64;
    int wn = (warp >> 1) * 32;

    float acc[4][4][4];
    #pragma unroll
    for (int i = 0; i < 4; i++)
        #pragma unroll
        for (int j = 0; j < 4; j++)
            #pragma unroll
            for (int c = 0; c < 4; c++) acc[i][j][c] = 0.f;

    for (int kt = 0; kt < K; kt += BK) {
        #pragma unroll
        for (int it = 0; it < 2; it++) {
            int i  = tid + it * 256;
            int m  = i >> 2, k4 = (i & 3) << 2;
            {
                int gr = bm + m;
                float4 a4 = make_float4(0.f,0.f,0.f,0.f);
                if (gr < M) a4 = *(const float4*)(A + (long)gr * K + kt + k4);
                float av[4] = {a4.x, a4.y, a4.z, a4.w};
                #pragma unroll
                for (int q = 0; q < 4; q++) {
                    unsigned hi = f2tf32(av[q]);
                    AsH[k4+q][m] = hi;
                    AsL[k4+q][m] = f2tf32(av[q] - __uint_as_float(hi));
                }
            }
            {
                int gr = bn + m;
                float4 w4 = make_float4(0.f,0.f,0.f,0.f);
                if (gr < N) w4 = *(const float4*)(W + (long)gr * K + kt + k4);
                float wv[4] = {w4.x, w4.y, w4.z, w4.w};
                #pragma unroll
                for (int q = 0; q < 4; q++) {
                    unsigned hi = f2tf32(wv[q]);
                    WsH[k4+q][m] = hi;
                    WsL[k4+q][m] = f2tf32(wv[q] - __uint_as_float(hi));
                }
            }
        }
        __syncthreads();

        #pragma unroll
        for (int kk = 0; kk < 2; kk++) {
            int kb = kk * 8;
            unsigned afH[4][4], afL[4][4];
            unsigned bfH[4][2], bfL[4][2];
            #pragma unroll
            for (int mt = 0; mt < 4; mt++) {
                int m0 = wm + mt * 16;
                afH[mt][0] = AsH[kb + t4    ][m0 + g    ];
                afH[mt][1] = AsH[kb + t4    ][m0 + g + 8];
                afH[mt][2] = AsH[kb + t4 + 4][m0 + g    ];
                afH[mt][3] = AsH[kb + t4 + 4][m0 + g + 8];
                afL[mt][0] = AsL[kb + t4    ][m0 + g    ];
                afL[mt][1] = AsL[kb + t4    ][m0 + g + 8];
                afL[mt][2] = AsL[kb + t4 + 4][m0 + g    ];
                afL[mt][3] = AsL[kb + t4 + 4][m0 + g + 8];
            }
            #pragma unroll
            for (int nt = 0; nt < 4; nt++) {
                int n0 = wn + nt * 8;
                bfH[nt][0] = WsH[kb + t4    ][n0 + g];
                bfH[nt][1] = WsH[kb + t4 + 4][n0 + g];
                bfL[nt][0] = WsL[kb + t4    ][n0 + g];
                bfL[nt][1] = WsL[kb + t4 + 4][n0 + g];
            }
            #pragma unroll
            for (int mt = 0; mt < 4; mt++)
                #pragma unroll
                for (int nt = 0; nt < 4; nt++) {
                    // lo terms first, hi*hi last (slightly better accumulation order)
                    asm volatile(
                        "mma.sync.aligned.m16n8k8.row.col.f32.tf32.tf32.f32 "
                        "{%0,%1,%2,%3}, {%4,%5,%6,%7}, {%8,%9}, {%0,%1,%2,%3};"
                        : "+f"(acc[mt][nt][0]), "+f"(acc[mt][nt][1]),
                          "+f"(acc[mt][nt][2]), "+f"(acc[mt][nt][3])
                        : "r"(afL[mt][0]), "r"(afL[mt][1]), "r"(afL[mt][2]), "r"(afL[mt][3]),
                          "r"(bfH[nt][0]), "r"(bfH[nt][1]));
                    asm volatile(
                        "mma.sync.aligned.m16n8k8.row.col.f32.tf32.tf32.f32 "
                        "{%0,%1,%2,%3}, {%4,%5,%6,%7}, {%8,%9}, {%0,%1,%2,%3};"
                        : "+f"(acc[mt][nt][0]), "+f"(acc[mt][nt][1]),
                          "+f"(acc[mt][nt][2]), "+f"(acc[mt][nt][3])
                        : "r"(afH[mt][0]), "r"(afH[mt][1]), "r"(afH[mt][2]), "r"(afH[mt][3]),
                          "r"(bfL[nt][0]), "r"(bfL[nt][1]));
                    asm volatile(
                        "mma.sync.aligned.m16n8k8.row.col.f32.tf32.tf32.f32 "
                        "{%0,%1,%2,%3}, {%4,%5,%6,%7}, {%8,%9}, {%0,%1,%2,%3};"
                        : "+f"(acc[mt][nt][0]), "+f"(acc[mt][nt][1]),
                          "+f"(acc[mt][nt][2]), "+f"(acc[mt][nt][3])
                        : "r"(afH[mt][0]), "r"(afH[mt][1]), "r"(afH[mt][2]), "r"(afH[mt][3]),
                          "r"(bfH[nt][0]), "r"(bfH[nt][1]));
                }
        }
        __syncthreads();
    }

    // epilogue
    #pragma unroll
    for (int mt = 0; mt < 4; mt++) {
        int row0 = bm + wm + mt * 16 + g;
        int row1 = row0 + 8;
        #pragma unroll
        for (int nt = 0; nt < 4; nt++) {
            int col = bn + wn + nt * 8 + t4 * 2;
            float bs0 = 0.f, bs1 = 0.f;
            if (bias && col < N)     bs0 = bias[col];
            if (bias && col + 1 < N) bs1 = bias[col + 1];
            #pragma unroll
            for (int half = 0; half < 2; half++) {
                int row = half ? row1 : row0;
                if (row >= M) continue;
                float v0 = acc[mt][nt][half * 2 + 0] + bs0;
                float v1 = acc[mt][nt][half * 2 + 1] + bs1;
                if (resid) {
                    if (col < N)     v0 += resid[(long)row * N + col];
                    if (col + 1 < N) v1 += resid[(long)row * N + col + 1];
                }
                if (act == 1) { v0 = gelu_exact(v0); v1 = gelu_exact(v1); }
                if (col < N)     C[(long)row * N + col]     = v0;
                if (col + 1 < N) C[(long)row * N + col + 1] = v1;
            }
        }
    }
}

// ---------------- attention: one block per (b,h) ----------------
#define ATTN_SMEM_FLOATS (NTOK*HD*2 + 64 + 208 + 256 + 8)
__global__ __launch_bounds__(256) void attn_kernel(
        const float* __restrict__ qkv, float* __restrict__ o,
        const float* __restrict__ alpha, const float* __restrict__ beta,
        const float* __restrict__ gamma, int poly) {
    extern __shared__ float sh[];
    float* Ks     = sh;
    float* Vs     = Ks + NTOK * HD;
    float* qs     = Vs + NTOK * HD;
    float* scores = qs + 64;
    float* part   = scores + 208;
    float* red    = part + 256;

    int b = blockIdx.x / HEADS;
    int hh = blockIdx.x - b * HEADS;
    int tid = threadIdx.x;

    const float* kbase = qkv + (long)(b * NTOK) * (3 * DIM) + DIM + hh * HD;
    const float* vbase = kbase + DIM;
    for (int i = tid; i < NTOK * (HD / 4); i += 256) {
        int n = i >> 4, d4 = (i & 15) << 2;
        ((float4*)Ks)[i] = *(const float4*)(kbase + (long)n * (3 * DIM) + d4);
        ((float4*)Vs)[i] = *(const float4*)(vbase + (long)n * (3 * DIM) + d4);
    }
    float ah = alpha[hh], bh = beta[hh], gh = gamma[hh];
    __syncthreads();

    for (int n = 0; n < NTOK; n++) {
        const float* qrow = qkv + (long)(b * NTOK + n) * (3 * DIM) + hh * HD;
        if (tid < HD) qs[tid] = qrow[tid];
        __syncthreads();

        float sraw = 0.f;
        if (tid < NTOK) {
            const float* kr = Ks + tid * HD;
            float d0 = 0.f;
            #pragma unroll 16
            for (int d = 0; d < HD; d++) d0 = fmaf(qs[d], kr[d], d0);
            sraw = d0 * ATTN_SCALE;
        }

        float denom;
        if (poly) {
            float val = 0.f;
            if (tid < NTOK) {
                val = fmaxf(fmaf(ah * sraw, sraw, fmaf(bh, sraw, gh)), 0.f);
                scores[tid] = val;
            }
            denom = blk_reduce256(tid < NTOK ? val : 0.f, false, red) + 1e-6f;
        } else {
            float mx = blk_reduce256(tid < NTOK ? sraw : -1e30f, true, red);
            float p = 0.f;
            if (tid < NTOK) { p = __expf(sraw - mx); scores[tid] = p; }
            denom = blk_reduce256(p, false, red);
        }
        float inv = 1.0f / denom;

        int ch = tid >> 6, d = tid & 63;
        float a0 = 0.f;
        int m0 = ch * 50, m1 = m0 + 50; if (m1 > NTOK) m1 = NTOK;
        #pragma unroll 4
        for (int m = m0; m < m1; m++) a0 = fmaf(scores[m], Vs[m * HD + d], a0);
        part[ch * 64 + d] = a0;
        __syncthreads();
        if (tid < 64) {
            float t = part[tid] + part[64 + tid] + part[128 + tid] + part[192 + tid];
            o[(long)(b * NTOK + n) * DIM + hh * HD + tid] = t * inv;
        }
        __syncthreads();
    }
}

// ---------------- host ----------------
static inline dim3 gemm_grid(int M, int N) {
    return dim3((N + BN - 1) / BN, (M + BM - 1) / BM);
}

extern "C" void kernel_launch(void* const* d_in, const int* in_sizes, int n_in,
                              void* d_out, int out_size) {
    const float* x        = (const float*)d_in[0];
    const float* patch_w  = (const float*)d_in[1];
    const float* patch_b  = (const float*)d_in[2];
    const float* cls_tok  = (const float*)d_in[3];
    const float* pos_emb  = (const float*)d_in[4];
    const float* ln1_w    = (const float*)d_in[5];
    const float* ln1_b    = (const float*)d_in[6];
    const float* qkv_w    = (const float*)d_in[7];
    const float* proj_w   = (const float*)d_in[8];
    const float* proj_b   = (const float*)d_in[9];
    const float* ln2_w    = (const float*)d_in[10];
    const float* ln2_b    = (const float*)d_in[11];
    const float* mlp_w1   = (const float*)d_in[12];
    const float* mlp_b1   = (const float*)d_in[13];
    const float* mlp_w2   = (const float*)d_in[14];
    const float* mlp_b2   = (const float*)d_in[15];
    const float* alpha    = (const float*)d_in[16];
    const float* beta     = (const float*)d_in[17];
    const float* gamma    = (const float*)d_in[18];
    const float* norm_w   = (const float*)d_in[19];
    const float* norm_b   = (const float*)d_in[20];
    const float* head_w   = (const float*)d_in[21];
    const float* head_b   = (const float*)d_in[22];
    float* out = (float*)d_out;

    float *ph, *hh, *lnb, *qkvb, *ob, *mb, *clsb;
    cudaGetSymbolAddress((void**)&ph,   g_patches);
    cudaGetSymbolAddress((void**)&hh,   g_h);
    cudaGetSymbolAddress((void**)&lnb,  g_ln);
    cudaGetSymbolAddress((void**)&qkvb, g_qkv);
    cudaGetSymbolAddress((void**)&ob,   g_attno);
    cudaGetSymbolAddress((void**)&mb,   g_mlp);
    cudaGetSymbolAddress((void**)&clsb, g_cls);

    const int attn_smem = ATTN_SMEM_FLOATS * sizeof(float);
    cudaFuncSetAttribute(attn_kernel, cudaFuncAttributeMaxDynamicSharedMemorySize, attn_smem);

    // 1) patchify + embed
    {
        int total = PROWS * DIM;
        gather_patches_kernel<<<(total + 255) / 256, 256>>>(x, ph);
        gemm_tc_kernel<<<gemm_grid(PROWS, DIM), 256>>>(ph, patch_w, patch_b, nullptr,
                                                       ob /*tok scratch*/, PROWS, DIM, DIM, 0);
        int tot2 = ROWS * DIM;
        embed_kernel<<<(tot2 + 255) / 256, 256>>>(ob, cls_tok, pos_emb, hh);
    }

    // 2) transformer layers
    for (int i = 0; i < DEPTH; i++) {
        int poly = (i % 2 == 0) ? 1 : 0;   // MASK = (T,F,T,F,...)
        ln_kernel<<<ROWS, 256>>>(hh, DIM, ln1_w + (long)i * DIM, ln1_b + (long)i * DIM, lnb);
        gemm_tc_kernel<<<gemm_grid(ROWS, 3 * DIM), 256>>>(lnb, qkv_w + (long)i * 3 * DIM * DIM,
                                                          nullptr, nullptr, qkvb,
                                                          ROWS, 3 * DIM, DIM, 0);
        attn_kernel<<<BATCH * HEADS, 256, attn_smem>>>(qkvb, ob,
                                                       alpha + (long)i * HEADS,
                                                       beta  + (long)i * HEADS,
                                                       gamma + (long)i * HEADS, poly);
        gemm_tc_kernel<<<gemm_grid(ROWS, DIM), 256>>>(ob, proj_w + (long)i * DIM * DIM,
                                                      proj_b + (long)i * DIM, hh, hh,
                                                      ROWS, DIM, DIM, 0);
        ln_kernel<<<ROWS, 256>>>(hh, DIM, ln2_w + (long)i * DIM, ln2_b + (long)i * DIM, lnb);
        gemm_tc_kernel<<<gemm_grid(ROWS, MLPD), 256>>>(lnb, mlp_w1 + (long)i * MLPD * DIM,
                                                       mlp_b1 + (long)i * MLPD, nullptr, mb,
                                                       ROWS, MLPD, DIM, 1 /*gelu*/);
        gemm_tc_kernel<<<gemm_grid(ROWS, DIM), 256>>>(mb, mlp_w2 + (long)i * DIM * MLPD,
                                                      mlp_b2 + (long)i * DIM, hh, hh,
                                                      ROWS, DIM, MLPD, 0);
    }

    // 3) final LN on cls rows + head
    ln_kernel<<<BATCH, 256>>>(hh, (long)NTOK * DIM, norm_w, norm_b, clsb);
    gemm_tc_kernel<<<gemm_grid(BATCH, 1000), 256>>>(clsb, head_w, head_b, nullptr, out,
                                                    BATCH, 1000, DIM, 0);
}

// round 10
// speedup vs baseline: 1.6396x; 1.4087x over previous
#include <cuda_runtime.h>
#include <cuda_bf16.h>
#include <math.h>

#define BATCH   32
#define NTOK    197
#define DIM     768
#define HEADS   12
#define HD      64
#define MLPD    3072
#define DEPTH   12
#define ROWS    (BATCH*NTOK)     // 6304
#define NPATCH  196
#define PROWS   (BATCH*NPATCH)   // 6272
#define ATTN_SCALE 0.125f

// ---------------- scratch (no cudaMalloc allowed) ----------------
__device__ float g_patches[PROWS*DIM];
__device__ float g_h     [ROWS*DIM];
__device__ float g_ln    [ROWS*DIM];
__device__ float g_qkv   [ROWS*3*DIM];
__device__ float g_attno [ROWS*DIM];
__device__ float g_mlp   [ROWS*MLPD];
__device__ float g_cls   [BATCH*DIM];

// ---------------- helpers ----------------
__device__ __forceinline__ float gelu_exact(float x) {
    return 0.5f * x * (1.0f + erff(x * 0.70710678118654752f));
}

// pack two floats as bf16x2: lo -> low 16 bits (even k), hi -> high 16 bits (odd k)
__device__ __forceinline__ unsigned pack2bf(float lo, float hi) {
    unsigned r;
    asm("cvt.rn.bf16x2.f32 %0, %1, %2;" : "=r"(r) : "f"(hi), "f"(lo));
    return r;
}
__device__ __forceinline__ float bf16hi_of(float x) {
    __nv_bfloat16 h = __float2bfloat16_rn(x);
    return __bfloat162float(h);
}

// block reduce over 256 threads. do_max=true -> max else sum.
__device__ __forceinline__ float blk_reduce256(float v, bool do_max, float* red) {
    #pragma unroll
    for (int off = 16; off; off >>= 1) {
        float o = __shfl_xor_sync(0xffffffffu, v, off);
        v = do_max ? fmaxf(v, o) : (v + o);
    }
    int w = threadIdx.x >> 5;
    if ((threadIdx.x & 31) == 0) red[w] = v;
    __syncthreads();
    if (threadIdx.x < 32) {
        v = red[threadIdx.x & 7];
        #pragma unroll
        for (int off = 4; off; off >>= 1) {
            float o = __shfl_xor_sync(0xffffffffu, v, off);
            v = do_max ? fmaxf(v, o) : (v + o);
        }
        if (threadIdx.x == 0) red[0] = v;
    }
    __syncthreads();
    float r = red[0];
    __syncthreads();
    return r;
}

// ---------------- patch gather ----------------
__global__ void gather_patches_kernel(const float* __restrict__ x, float* __restrict__ P) {
    int idx = blockIdx.x * blockDim.x + threadIdx.x;
    int total = PROWS * DIM;
    if (idx >= total) return;
    int m = idx / DIM, k = idx - m * DIM;
    int b = m / NPATCH, t = m - b * NPATCH;
    int ph = t / 14, pw = t - ph * 14;
    int c = k >> 8, r = k & 255;
    int py = r >> 4, px = r & 15;
    int h = ph * 16 + py, w = pw * 16 + px;
    P[idx] = x[(((long)b * 3 + c) * 224 + h) * 224 + w];
}

// ---------------- assemble h = [cls ; tok] + pos ----------------
__global__ void embed_kernel(const float* __restrict__ tok, const float* __restrict__ cls,
                             const float* __restrict__ pos, float* __restrict__ h) {
    int idx = blockIdx.x * blockDim.x + threadIdx.x;
    int total = ROWS * DIM;
    if (idx >= total) return;
    int rd = idx % (NTOK * DIM);
    int b  = idx / (NTOK * DIM);
    int n  = rd / DIM, d = rd - n * DIM;
    float base = (n == 0) ? cls[d] : tok[((long)b * NPATCH + (n - 1)) * DIM + d];
    h[idx] = base + pos[n * DIM + d];
}

// ---------------- layernorm ----------------
__global__ void ln_kernel(const float* __restrict__ x, long row_stride,
                          const float* __restrict__ w, const float* __restrict__ b,
                          float* __restrict__ y) {
    __shared__ float red[8];
    long row = blockIdx.x;
    const float* xr = x + row * row_stride;
    int tid = threadIdx.x;
    float v[3], s = 0.f, ss = 0.f;
    #pragma unroll
    for (int i = 0; i < 3; i++) {
        float t = xr[tid + i * 256];
        v[i] = t; s += t; ss += t * t;
    }
    s  = blk_reduce256(s,  false, red);
    ss = blk_reduce256(ss, false, red);
    float mu  = s * (1.0f / 768.0f);
    float var = ss * (1.0f / 768.0f) - mu * mu;
    float inv = rsqrtf(var + 1e-5f);
    #pragma unroll
    for (int i = 0; i < 3; i++) {
        int d = tid + i * 256;
        y[row * DIM + d] = (v[i] - mu) * inv * w[d] + b[d];
    }
}

// ---------------- 2-split BF16 tensor-core GEMM ----------------
// C[M,N] = A[M,K] @ W[N,K]^T (+bias)(+resid)(gelu)
// block tile 128x128x16, 8 warps, each warp 64x32 via m16n8k16 bf16 mma.
// x = hi + lo (both bf16); product = aH*bH + aH*bL + aL*bH  (~16 mantissa bits)
#define BM 128
#define BN 128
#define BK 16
#define SPITCH 136   // pitch in uint32; 136 % 32 == 8 -> conflict-free frag loads

__global__ __launch_bounds__(256) void gemm_tc_kernel(
        const float* __restrict__ A, const float* __restrict__ W,
        const float* __restrict__ bias, const float* __restrict__ resid,
        float* __restrict__ C, int M, int N, int K, int act /*1=gelu*/) {
    // packed bf16x2 along k: index [k2][m], k2 = k/2 in 0..7
    __shared__ unsigned AsH[8][SPITCH];
    __shared__ unsigned AsL[8][SPITCH];
    __shared__ unsigned WsH[8][SPITCH];
    __shared__ unsigned WsL[8][SPITCH];

    int bm = blockIdx.y * BM;
    int bn = blockIdx.x * BN;
    int tid  = threadIdx.x;
    int warp = tid >> 5;
    int lane = tid & 31;
    int g    = lane >> 2;    // 0..7
    int t4   = lane & 3;     // 0..3

    int wm = (warp & 1) * 64;
    int wn = (warp >> 1) * 32;

    // global-load coords for this thread (2 float4 per array per tile)
    int lm0 = tid >> 2;                 // 0..63   (it=0)
    int lm1 = (tid + 256) >> 2;         // 64..127 (it=1)
    int lk4 = (tid & 3) << 2;           // 0,4,8,12

    float acc[4][4][4];
    #pragma unroll
    for (int i = 0; i < 4; i++)
        #pragma unroll
        for (int j = 0; j < 4; j++)
            #pragma unroll
            for (int c = 0; c < 4; c++) acc[i][j][c] = 0.f;

    // prefetch tile 0
    float4 pA[2], pW[2];
    {
        int gr0 = bm + lm0, gr1 = bm + lm1;
        pA[0] = (gr0 < M) ? *(const float4*)(A + (long)gr0 * K + lk4) : make_float4(0,0,0,0);
        pA[1] = (gr1 < M) ? *(const float4*)(A + (long)gr1 * K + lk4) : make_float4(0,0,0,0);
        int gc0 = bn + lm0, gc1 = bn + lm1;
        pW[0] = (gc0 < N) ? *(const float4*)(W + (long)gc0 * K + lk4) : make_float4(0,0,0,0);
        pW[1] = (gc1 < N) ? *(const float4*)(W + (long)gc1 * K + lk4) : make_float4(0,0,0,0);
    }

    int k2base = lk4 >> 1;   // 0,2,4,6

    for (int kt = 0; kt < K; kt += BK) {
        // store prefetched tile into smem (split + pack)
        #pragma unroll
        for (int it = 0; it < 2; it++) {
            int m = it ? lm1 : lm0;
            float av[4] = {pA[it].x, pA[it].y, pA[it].z, pA[it].w};
            float wv[4] = {pW[it].x, pW[it].y, pW[it].z, pW[it].w};
            float ah0 = bf16hi_of(av[0]), ah1 = bf16hi_of(av[1]);
            float ah2 = bf16hi_of(av[2]), ah3 = bf16hi_of(av[3]);
            AsH[k2base  ][m] = pack2bf(ah0, ah1);
            AsH[k2base+1][m] = pack2bf(ah2, ah3);
            AsL[k2base  ][m] = pack2bf(av[0]-ah0, av[1]-ah1);
            AsL[k2base+1][m] = pack2bf(av[2]-ah2, av[3]-ah3);
            float wh0 = bf16hi_of(wv[0]), wh1 = bf16hi_of(wv[1]);
            float wh2 = bf16hi_of(wv[2]), wh3 = bf16hi_of(wv[3]);
            WsH[k2base  ][m] = pack2bf(wh0, wh1);
            WsH[k2base+1][m] = pack2bf(wh2, wh3);
            WsL[k2base  ][m] = pack2bf(wv[0]-wh0, wv[1]-wh1);
            WsL[k2base+1][m] = pack2bf(wv[2]-wh2, wv[3]-wh3);
        }
        __syncthreads();

        // prefetch next tile (overlaps with MMA work below)
        int ktn = kt + BK;
        if (ktn < K) {
            int gr0 = bm + lm0, gr1 = bm + lm1;
            pA[0] = (gr0 < M) ? *(const float4*)(A + (long)gr0 * K + ktn + lk4) : make_float4(0,0,0,0);
            pA[1] = (gr1 < M) ? *(const float4*)(A + (long)gr1 * K + ktn + lk4) : make_float4(0,0,0,0);
            int gc0 = bn + lm0, gc1 = bn + lm1;
            pW[0] = (gc0 < N) ? *(const float4*)(W + (long)gc0 * K + ktn + lk4) : make_float4(0,0,0,0);
            pW[1] = (gc1 < N) ? *(const float4*)(W + (long)gc1 * K + ktn + lk4) : make_float4(0,0,0,0);
        }

        // one k16 step: fragment loads + 3-term compensated MMA
        unsigned afH[4][4], afL[4][4];
        unsigned bfH[4][2], bfL[4][2];
        #pragma unroll
        for (int mt = 0; mt < 4; mt++) {
            int m0 = wm + mt * 16;
            afH[mt][0] = AsH[t4    ][m0 + g    ];
            afH[mt][1] = AsH[t4    ][m0 + g + 8];
            afH[mt][2] = AsH[t4 + 4][m0 + g    ];
            afH[mt][3] = AsH[t4 + 4][m0 + g + 8];
            afL[mt][0] = AsL[t4    ][m0 + g    ];
            afL[mt][1] = AsL[t4    ][m0 + g + 8];
            afL[mt][2] = AsL[t4 + 4][m0 + g    ];
            afL[mt][3] = AsL[t4 + 4][m0 + g + 8];
        }
        #pragma unroll
        for (int nt = 0; nt < 4; nt++) {
            int n0 = wn + nt * 8;
            bfH[nt][0] = WsH[t4    ][n0 + g];
            bfH[nt][1] = WsH[t4 + 4][n0 + g];
            bfL[nt][0] = WsL[t4    ][n0 + g];
            bfL[nt][1] = WsL[t4 + 4][n0 + g];
        }
        #pragma unroll
        for (int mt = 0; mt < 4; mt++)
            #pragma unroll
            for (int nt = 0; nt < 4; nt++) {
                asm volatile(
                    "mma.sync.aligned.m16n8k16.row.col.f32.bf16.bf16.f32 "
                    "{%0,%1,%2,%3}, {%4,%5,%6,%7}, {%8,%9}, {%0,%1,%2,%3};"
                    : "+f"(acc[mt][nt][0]), "+f"(acc[mt][nt][1]),
                      "+f"(acc[mt][nt][2]), "+f"(acc[mt][nt][3])
                    : "r"(afL[mt][0]), "r"(afL[mt][1]), "r"(afL[mt][2]), "r"(afL[mt][3]),
                      "r"(bfH[nt][0]), "r"(bfH[nt][1]));
                asm volatile(
                    "mma.sync.aligned.m16n8k16.row.col.f32.bf16.bf16.f32 "
                    "{%0,%1,%2,%3}, {%4,%5,%6,%7}, {%8,%9}, {%0,%1,%2,%3};"
                    : "+f"(acc[mt][nt][0]), "+f"(acc[mt][nt][1]),
                      "+f"(acc[mt][nt][2]), "+f"(acc[mt][nt][3])
                    : "r"(afH[mt][0]), "r"(afH[mt][1]), "r"(afH[mt][2]), "r"(afH[mt][3]),
                      "r"(bfL[nt][0]), "r"(bfL[nt][1]));
                asm volatile(
                    "mma.sync.aligned.m16n8k16.row.col.f32.bf16.bf16.f32 "
                    "{%0,%1,%2,%3}, {%4,%5,%6,%7}, {%8,%9}, {%0,%1,%2,%3};"
                    : "+f"(acc[mt][nt][0]), "+f"(acc[mt][nt][1]),
                      "+f"(acc[mt][nt][2]), "+f"(acc[mt][nt][3])
                    : "r"(afH[mt][0]), "r"(afH[mt][1]), "r"(afH[mt][2]), "r"(afH[mt][3]),
                      "r"(bfH[nt][0]), "r"(bfH[nt][1]));
            }
        __syncthreads();
    }

    // epilogue
    #pragma unroll
    for (int mt = 0; mt < 4; mt++) {
        int row0 = bm + wm + mt * 16 + g;
        int row1 = row0 + 8;
        #pragma unroll
        for (int nt = 0; nt < 4; nt++) {
            int col = bn + wn + nt * 8 + t4 * 2;
            float bs0 = 0.f, bs1 = 0.f;
            if (bias && col < N)     bs0 = bias[col];
            if (bias && col + 1 < N) bs1 = bias[col + 1];
            #pragma unroll
            for (int half = 0; half < 2; half++) {
                int row = half ? row1 : row0;
                if (row >= M) continue;
                float v0 = acc[mt][nt][half * 2 + 0] + bs0;
                float v1 = acc[mt][nt][half * 2 + 1] + bs1;
                if (resid) {
                    if (col < N)     v0 += resid[(long)row * N + col];
                    if (col + 1 < N) v1 += resid[(long)row * N + col + 1];
                }
                if (act == 1) { v0 = gelu_exact(v0); v1 = gelu_exact(v1); }
                if (col < N)     C[(long)row * N + col]     = v0;
                if (col + 1 < N) C[(long)row * N + col + 1] = v1;
            }
        }
    }
}

// ---------------- attention: one block per (b,h) ----------------
#define ATTN_SMEM_FLOATS (NTOK*HD*2 + 64 + 208 + 256 + 8)
__global__ __launch_bounds__(256) void attn_kernel(
        const float* __restrict__ qkv, float* __restrict__ o,
        const float* __restrict__ alpha, const float* __restrict__ beta,
        const float* __restrict__ gamma, int poly) {
    extern __shared__ float sh[];
    float* Ks     = sh;
    float* Vs     = Ks + NTOK * HD;
    float* qs     = Vs + NTOK * HD;
    float* scores = qs + 64;
    float* part   = scores + 208;
    float* red    = part + 256;

    int b = blockIdx.x / HEADS;
    int hh = blockIdx.x - b * HEADS;
    int tid = threadIdx.x;

    const float* kbase = qkv + (long)(b * NTOK) * (3 * DIM) + DIM + hh * HD;
    const float* vbase = kbase + DIM;
    for (int i = tid; i < NTOK * (HD / 4); i += 256) {
        int n = i >> 4, d4 = (i & 15) << 2;
        ((float4*)Ks)[i] = *(const float4*)(kbase + (long)n * (3 * DIM) + d4);
        ((float4*)Vs)[i] = *(const float4*)(vbase + (long)n * (3 * DIM) + d4);
    }
    float ah = alpha[hh], bh = beta[hh], gh = gamma[hh];
    __syncthreads();

    for (int n = 0; n < NTOK; n++) {
        const float* qrow = qkv + (long)(b * NTOK + n) * (3 * DIM) + hh * HD;
        if (tid < HD) qs[tid] = qrow[tid];
        __syncthreads();

        float sraw = 0.f;
        if (tid < NTOK) {
            const float* kr = Ks + tid * HD;
            float d0 = 0.f;
            #pragma unroll 16
            for (int d = 0; d < HD; d++) d0 = fmaf(qs[d], kr[d], d0);
            sraw = d0 * ATTN_SCALE;
        }

        float denom;
        if (poly) {
            float val = 0.f;
            if (tid < NTOK) {
                val = fmaxf(fmaf(ah * sraw, sraw, fmaf(bh, sraw, gh)), 0.f);
                scores[tid] = val;
            }
            denom = blk_reduce256(tid < NTOK ? val : 0.f, false, red) + 1e-6f;
        } else {
            float mx = blk_reduce256(tid < NTOK ? sraw : -1e30f, true, red);
            float p = 0.f;
            if (tid < NTOK) { p = __expf(sraw - mx); scores[tid] = p; }
            denom = blk_reduce256(p, false, red);
        }
        float inv = 1.0f / denom;

        int ch = tid >> 6, d = tid & 63;
        float a0 = 0.f;
        int m0 = ch * 50, m1 = m0 + 50; if (m1 > NTOK) m1 = NTOK;
        #pragma unroll 4
        for (int m = m0; m < m1; m++) a0 = fmaf(scores[m], Vs[m * HD + d], a0);
        part[ch * 64 + d] = a0;
        __syncthreads();
        if (tid < 64) {
            float t = part[tid] + part[64 + tid] + part[128 + tid] + part[192 + tid];
            o[(long)(b * NTOK + n) * DIM + hh * HD + tid] = t * inv;
        }
        __syncthreads();
    }
}

// ---------------- host ----------------
static inline dim3 gemm_grid(int M, int N) {
    return dim3((N + BN - 1) / BN, (M + BM - 1) / BM);
}

extern "C" void kernel_launch(void* const* d_in, const int* in_sizes, int n_in,
                              void* d_out, int out_size) {
    const float* x        = (const float*)d_in[0];
    const float* patch_w  = (const float*)d_in[1];
    const float* patch_b  = (const float*)d_in[2];
    const float* cls_tok  = (const float*)d_in[3];
    const float* pos_emb  = (const float*)d_in[4];
    const float* ln1_w    = (const float*)d_in[5];
    const float* ln1_b    = (const float*)d_in[6];
    const float* qkv_w    = (const float*)d_in[7];
    const float* proj_w   = (const float*)d_in[8];
    const float* proj_b   = (const float*)d_in[9];
    const float* ln2_w    = (const float*)d_in[10];
    const float* ln2_b    = (const float*)d_in[11];
    const float* mlp_w1   = (const float*)d_in[12];
    const float* mlp_b1   = (const float*)d_in[13];
    const float* mlp_w2   = (const float*)d_in[14];
    const float* mlp_b2   = (const float*)d_in[15];
    const float* alpha    = (const float*)d_in[16];
    const float* beta     = (const float*)d_in[17];
    const float* gamma    = (const float*)d_in[18];
    const float* norm_w   = (const float*)d_in[19];
    const float* norm_b   = (const float*)d_in[20];
    const float* head_w   = (const float*)d_in[21];
    const float* head_b   = (const float*)d_in[22];
    float* out = (float*)d_out;

    float *ph, *hh, *lnb, *qkvb, *ob, *mb, *clsb;
    cudaGetSymbolAddress((void**)&ph,   g_patches);
    cudaGetSymbolAddress((void**)&hh,   g_h);
    cudaGetSymbolAddress((void**)&lnb,  g_ln);
    cudaGetSymbolAddress((void**)&qkvb, g_qkv);
    cudaGetSymbolAddress((void**)&ob,   g_attno);
    cudaGetSymbolAddress((void**)&mb,   g_mlp);
    cudaGetSymbolAddress((void**)&clsb, g_cls);

    const int attn_smem = ATTN_SMEM_FLOATS * sizeof(float);
    cudaFuncSetAttribute(attn_kernel, cudaFuncAttributeMaxDynamicSharedMemorySize, attn_smem);

    // 1) patchify + embed
    {
        int total = PROWS * DIM;
        gather_patches_kernel<<<(total + 255) / 256, 256>>>(x, ph);
        gemm_tc_kernel<<<gemm_grid(PROWS, DIM), 256>>>(ph, patch_w, patch_b, nullptr,
                                                       ob /*tok scratch*/, PROWS, DIM, DIM, 0);
        int tot2 = ROWS * DIM;
        embed_kernel<<<(tot2 + 255) / 256, 256>>>(ob, cls_tok, pos_emb, hh);
    }

    // 2) transformer layers
    for (int i = 0; i < DEPTH; i++) {
        int poly = (i % 2 == 0) ? 1 : 0;   // MASK = (T,F,T,F,...)
        ln_kernel<<<ROWS, 256>>>(hh, DIM, ln1_w + (long)i * DIM, ln1_b + (long)i * DIM, lnb);
        gemm_tc_kernel<<<gemm_grid(ROWS, 3 * DIM), 256>>>(lnb, qkv_w + (long)i * 3 * DIM * DIM,
                                                          nullptr, nullptr, qkvb,
                                                          ROWS, 3 * DIM, DIM, 0);
        attn_kernel<<<BATCH * HEADS, 256, attn_smem>>>(qkvb, ob,
                                                       alpha + (long)i * HEADS,
                                                       beta  + (long)i * HEADS,
                                                       gamma + (long)i * HEADS, poly);
        gemm_tc_kernel<<<gemm_grid(ROWS, DIM), 256>>>(ob, proj_w + (long)i * DIM * DIM,
                                                      proj_b + (long)i * DIM, hh, hh,
                                                      ROWS, DIM, DIM, 0);
        ln_kernel<<<ROWS, 256>>>(hh, DIM, ln2_w + (long)i * DIM, ln2_b + (long)i * DIM, lnb);
        gemm_tc_kernel<<<gemm_grid(ROWS, MLPD), 256>>>(lnb, mlp_w1 + (long)i * MLPD * DIM,
                                                       mlp_b1 + (long)i * MLPD, nullptr, mb,
                                                       ROWS, MLPD, DIM, 1 /*gelu*/);
        gemm_tc_kernel<<<gemm_grid(ROWS, DIM), 256>>>(mb, mlp_w2 + (long)i * DIM * MLPD,
                                                      mlp_b2 + (long)i * DIM, hh, hh,
                                                      ROWS, DIM, MLPD, 0);
    }

    // 3) final LN on cls rows + head
    ln_kernel<<<BATCH, 256>>>(hh, (long)NTOK * DIM, norm_w, norm_b, clsb);
    gemm_tc_kernel<<<gemm_grid(BATCH, 1000), 256>>>(clsb, head_w, head_b, nullptr, out,
                                                    BATCH, 1000, DIM, 0);
}